// round 5
// baseline (speedup 1.0000x reference)
#include <cuda_runtime.h>
#include <math.h>

#define B_   64
#define C_   8
#define H_   256
#define W_   256
#define N_   200
#define NT   (B_ * N_)          // 12800 targets
#define HW   (H_ * W_)          // 65536
#define NUM_CLASSES 3

#define THREADS 96
#define BLOCKS  148                     // one CTA per SM
#define NWARPS_TOT (BLOCKS * (THREADS / 32))   // 444
#define NWARPS_WORK (NT / 32)           // 400 warps carry targets, exact

// Per-warp partials (fully overwritten each run) + ticket counter.
__device__ float        g_part[NWARPS_TOT][3];
__device__ unsigned int g_count;   // zero at load; reset by finalizing warp each run

__device__ __forceinline__ float softplus_f(float x) {
    return fmaxf(x, 0.0f) + log1pf(expf(-fabsf(x)));
}

__device__ __forceinline__ float warp_sum_f(float v) {
    #pragma unroll
    for (int off = 16; off > 0; off >>= 1)
        v += __shfl_xor_sync(0xFFFFFFFFu, v, off);
    return v;
}

__device__ __forceinline__ double warp_sum_d(double v) {
    #pragma unroll
    for (int off = 16; off > 0; off >>= 1)
        v += __shfl_xor_sync(0xFFFFFFFFu, v, off);
    return v;
}

__global__ void __launch_bounds__(THREADS) yolo_fused_kernel(
    const float* __restrict__ pred,
    const float* __restrict__ targets,
    float* __restrict__ out)
{
    int lane = threadIdx.x & 31;
    int w    = blockIdx.x * (THREADS / 32) + (threadIdx.x >> 5);  // global warp id

    float bbox = 0.0f, obj = 0.0f, clsl = 0.0f;

    if (w < NWARPS_WORK) {
        int i = w * 32 + lane;          // target index, always < NT
        int b = i / N_;
        const float* t = targets + (size_t)i * 5;
        float cid = t[0];
        float c0 = t[1], c1 = t[2], c2 = t[3], c3 = t[4];

        float csum = ((c0 + c1) + c2) + c3;
        int xp = (int)(c0 * (float)W_);
        int yp = (int)(c1 * (float)H_);
        bool valid = (cid >= 0.0f) && (csum > 0.0f);
        bool inb = (xp >= 0) && (xp < W_) && (yp >= 0) && (yp < H_);

        if (valid && inb) {
            int xs = min(max(xp, 0), W_ - 1);
            int ys = min(max(yp, 0), H_ - 1);
            const float* base = pred + ((size_t)b * C_) * HW + (size_t)ys * W_ + xs;

            float p[C_];
            #pragma unroll
            for (int c = 0; c < C_; c++)
                p[c] = __ldg(base + (size_t)c * HW);   // 8 independent loads, MLP=8

            float d0 = p[0] - c0, d1 = p[1] - c1, d2 = p[2] - c2, d3 = p[3] - c3;
            bbox = 0.25f * (d0 * d0 + d1 * d1 + d2 * d2 + d3 * d3);

            obj = softplus_f(-p[4]);   // bce(p4, 1)

            int k = (int)fmaxf(cid, 0.0f);
            float s = 0.0f;
            #pragma unroll
            for (int c = 0; c < NUM_CLASSES; c++) {
                float l = p[5 + c];
                float z = (c == k) ? 1.0f : 0.0f;
                s += softplus_f(l) - l * z;
            }
            clsl = s * (1.0f / 3.0f);
        }
    }

    // Warp-level reduction only; no __syncthreads anywhere.
    bbox = warp_sum_f(bbox);
    obj  = warp_sum_f(obj);
    clsl = warp_sum_f(clsl);

    unsigned int old = 0;
    if (lane == 0) {
        g_part[w][0] = bbox;
        g_part[w][1] = obj;
        g_part[w][2] = clsl;
        __threadfence();
        old = atomicAdd(&g_count, 1u);
    }
    old = __shfl_sync(0xFFFFFFFFu, old, 0);

    if (old == NWARPS_TOT - 1) {
        // Last-arriving warp: deterministic lane-strided gather + shuffle tree.
        double bs = 0.0, os = 0.0, cs = 0.0;
        #pragma unroll
        for (int j = lane; j < NWARPS_TOT; j += 32) {
            bs += (double)g_part[j][0];
            os += (double)g_part[j][1];
            cs += (double)g_part[j][2];
        }
        bs = warp_sum_d(bs);
        os = warp_sum_d(os);
        cs = warp_sum_d(cs);
        if (lane == 0) {
            g_count = 0;   // reset for next graph replay
            double total = 0.05 * bs + 1.0 * os + 0.5 * cs;
            out[0] = (float)total;
            out[1] = (float)bs;
            out[2] = (float)os;
            out[3] = (float)cs;
        }
    }
}

extern "C" void kernel_launch(void* const* d_in, const int* in_sizes, int n_in,
                              void* d_out, int out_size)
{
    const float* pred    = (const float*)d_in[0];
    const float* targets = (const float*)d_in[1];
    float* out = (float*)d_out;

    yolo_fused_kernel<<<BLOCKS, THREADS>>>(pred, targets, out);
}